// round 13
// baseline (speedup 1.0000x reference)
#include <cuda_runtime.h>
#include <cstdint>

#define Bb 8
#define Cc 256
#define Nn 4096
#define Dd 32

typedef unsigned long long ull;

// ======================= helpers =======================
__device__ __forceinline__ void fma2(ull& d, ull a, ull b) {
    asm("fma.rn.f32x2 %0, %1, %2, %0;" : "+l"(d) : "l"(a), "l"(b));
}
__device__ __forceinline__ ull dup2(float v) {
    ull r; asm("mov.b64 %0, {%1, %1};" : "=l"(r) : "f"(v)); return r;
}
__device__ __forceinline__ float2 unpk2(ull v) {
    float2 r; asm("mov.b64 {%0, %1}, %2;" : "=f"(r.x), "=f"(r.y) : "l"(v)); return r;
}
__device__ __forceinline__ float tf32r(float v) {
    uint32_t u; asm("cvt.rna.tf32.f32 %0, %1;" : "=r"(u) : "f"(v));
    return __uint_as_float(u);
}
__device__ __forceinline__ uint32_t tf32u(float v) {
    uint32_t u; asm("cvt.rna.tf32.f32 %0, %1;" : "=r"(u) : "f"(v));
    return u;
}
// k-fragment permutation within a 32-block: fragment words become contiguous
__device__ __host__ __forceinline__ int perm32(int k) {
    return ((k & 3) << 3) | (k & 4) | (k >> 3);
}

// portable tensor-core mma (sm_80+, assembles at compute_103)
#define MMA_TF32(d, a0, a1, a2, a3, b0, b1) \
    asm volatile("mma.sync.aligned.m16n8k8.row.col.f32.tf32.tf32.f32 " \
        "{%0,%1,%2,%3}, {%4,%5,%6,%7}, {%8,%9}, {%0,%1,%2,%3};" \
        : "+f"((d)[0]), "+f"((d)[1]), "+f"((d)[2]), "+f"((d)[3]) \
        : "r"(a0), "r"(a1), "r"(a2), "r"(a3), "r"(b0), "r"(b1))

// ---- scratch (static device globals) ----
__device__ float g_qT[Bb * Nn * Dd];          // [b][n][d_perm]  tf32
__device__ float g_kT[Bb * Nn * Dd];          // [b][n][d_perm]  tf32
__device__ float g_vC[Bb * Cc * Nn];          // [b][c][n: perm32 in 32-blocks] tf32
__device__ float g_ga[Bb * Cc];               // gate activations

// =====================================================================
// Kernel 1: fused projections q/k/v (f32x2 mainloop). grid (64, 8), 256 thr.
// =====================================================================
#define PROJ_SMEM ((256 * 66 + 64 * 65) * 4)

__global__ __launch_bounds__(256, 2)
void proj_kernel(const float* __restrict__ x,
                 const float* __restrict__ Wq, const float* __restrict__ bq,
                 const float* __restrict__ Wk, const float* __restrict__ bk,
                 const float* __restrict__ Wv, const float* __restrict__ bv)
{
    extern __shared__ float sm[];
    float* xs = sm;              // [256][66]
    float* ws = sm + 256 * 66;   // [64][65]

    const int b  = blockIdx.y;
    const int n0 = blockIdx.x * 64;
    const int t  = threadIdx.x;
    const int tor = t >> 4;
    const int tnc = t & 15;

    const float* xb = x + (size_t)b * Cc * Nn;
#pragma unroll
    for (int i = 0; i < 64; ++i) {
        int idx = t + i * 256;
        int c = idx >> 6, j = idx & 63;
        xs[c * 66 + j] = xb[c * Nn + n0 + j];
    }

    for (int ot = 0; ot < 5; ++ot) {
        ull a2[4][2];
#pragma unroll
        for (int i = 0; i < 4; ++i) { a2[i][0] = 0ULL; a2[i][1] = 0ULL; }

        for (int cc = 0; cc < 4; ++cc) {
            __syncthreads();
#pragma unroll
            for (int i = 0; i < 16; ++i) {
                int idx = t + i * 256;
                int oo = idx >> 6, cj = idx & 63;
                int og = ot * 64 + oo;
                const float* wrow = (og < 32) ? (Wq + og * 256)
                                  : (og < 64) ? (Wk + (og - 32) * 256)
                                              : (Wv + (og - 64) * 256);
                ws[oo * 65 + cj] = wrow[cc * 64 + cj];
            }
            __syncthreads();
#pragma unroll 8
            for (int kk = 0; kk < 64; ++kk) {
                ull xv0 = *reinterpret_cast<const ull*>(&xs[(cc * 64 + kk) * 66 + tnc * 4]);
                ull xv1 = *reinterpret_cast<const ull*>(&xs[(cc * 64 + kk) * 66 + tnc * 4 + 2]);
#pragma unroll
                for (int i = 0; i < 4; ++i) {
                    ull wd = dup2(ws[(tor * 4 + i) * 65 + kk]);
                    fma2(a2[i][0], wd, xv0);
                    fma2(a2[i][1], wd, xv1);
                }
            }
        }
#pragma unroll
        for (int i = 0; i < 4; ++i) {
            int og = ot * 64 + tor * 4 + i;
            float vals[4];
            float2 u0 = unpk2(a2[i][0]), u1 = unpk2(a2[i][1]);
            vals[0] = u0.x; vals[1] = u0.y; vals[2] = u1.x; vals[3] = u1.y;
            if (og < 64) {
                int dp = (og < 32) ? perm32(og) : perm32(og - 32);
#pragma unroll
                for (int j = 0; j < 4; ++j) {
                    int n = n0 + tnc * 4 + j;
                    if (og < 32)
                        g_qT[(b * Nn + n) * Dd + dp] = tf32r(vals[j] + bq[og]);
                    else
                        g_kT[(b * Nn + n) * Dd + dp] = tf32r(vals[j] + bk[og - 32]);
                }
            } else {
                int c = og - 64;
                float bias = bv[c];
#pragma unroll
                for (int j = 0; j < 4; ++j) {
                    int n = n0 + tnc * 4 + j;
                    int np = (n & ~31) | perm32(n & 31);
                    g_vC[((size_t)b * Cc + c) * Nn + np] = tf32r(vals[j] + bias);
                }
            }
        }
    }
}

// =====================================================================
// Kernel 2: gated pooling branch -> g_ga[b][c]
// =====================================================================
__global__ __launch_bounds__(256)
void gate_kernel(const float* __restrict__ x,
                 const float* __restrict__ Wg1, const float* __restrict__ bg1,
                 const float* __restrict__ Wg2, const float* __restrict__ bg2)
{
    __shared__ float gp[256];
    __shared__ float h[32];
    const int b = blockIdx.x;
    const int t = threadIdx.x;
    const int w = t >> 5, lane = t & 31;

    for (int cr = 0; cr < 32; ++cr) {
        int c = w * 32 + cr;
        const float* row = x + ((size_t)b * Cc + c) * Nn;
        float s = 0.f;
        for (int i = lane; i < Nn; i += 32) s += row[i];
#pragma unroll
        for (int o = 16; o; o >>= 1) s += __shfl_down_sync(0xffffffffu, s, o);
        if (lane == 0) gp[c] = s * (1.0f / (float)Nn);
    }
    __syncthreads();
    if (t < 32) {
        float s = bg1[t];
        const float* wr = Wg1 + t * 256;
        for (int c = 0; c < 256; ++c) s = fmaf(wr[c], gp[c], s);
        h[t] = fmaxf(s, 0.f);
    }
    __syncthreads();
    {
        float s = bg2[t];
        const float* wr = Wg2 + t * 32;
#pragma unroll
        for (int o = 0; o < 32; ++o) s = fmaf(wr[o], h[o], s);
        g_ga[b * Cc + t] = 1.0f / (1.0f + __expf(-s));
    }
}

// =====================================================================
// Kernel 3: mma.sync tf32 flash, BM=64, BN=64, LDS.128 permuted fragments.
// grid (64, 8), 256 threads, 64 chunks.
// smem (words): Qs[64][36] | Ks[64][36] | Vs[256][68] | Ps[64][68] | lred[128]
//   k=64 rows (Vs, Ps): two perm32 blocks at word 0 and +32, stride 68.
// =====================================================================
#define QS_W   0
#define KS_W   2304
#define VS_W   4608
#define PS_W   22016
#define LR_W   26368
#define FLASH_SMEM ((26368 + 128) * 4)

__global__ __launch_bounds__(256, 2)
void flash_mma_kernel(const float* __restrict__ x,
                      const float* __restrict__ gammaPtr,
                      float* __restrict__ out)
{
    extern __shared__ float smf[];
    uint32_t* SU = (uint32_t*)smf;

    const int t    = threadIdx.x;
    const int wid  = t >> 5;
    const int lane = t & 31;
    const int g    = lane >> 2;
    const int tg   = lane & 3;
    const int wr   = wid >> 1;      // row band: rows 16*wr .. +15
    const int wc   = wid & 1;       // col half
    const int b    = blockIdx.y;
    const int n0   = blockIdx.x * 64;

    const int r0 = 16 * wr + g;
    const int r1 = r0 + 8;

    const float* vbase = g_vC + (size_t)b * Cc * Nn;
    const float* kbase = g_kT + (size_t)b * Nn * Dd;

    // ---- stage Q (perm'd) -> smem, extract A-fragments (held all kernel) ----
#pragma unroll
    for (int i = 0; i < 2; ++i) {
        int idx4 = t + i * 256;
        int r = idx4 >> 3, d4 = (idx4 & 7) * 4;
        float4 v = *reinterpret_cast<const float4*>(
            &g_qT[((size_t)b * Nn + n0 + r) * Dd + d4]);
        *reinterpret_cast<float4*>(&smf[QS_W + r * 36 + d4]) = v;
    }
    __syncthreads();
    uint4 qa0 = *(const uint4*)&SU[QS_W + r0 * 36 + tg * 8];
    uint4 qa1 = *(const uint4*)&SU[QS_W + r1 * 36 + tg * 8];
    uint4 qa2 = *(const uint4*)&SU[QS_W + r0 * 36 + tg * 8 + 4];
    uint4 qa3 = *(const uint4*)&SU[QS_W + r1 * 36 + tg * 8 + 4];
    const uint32_t* qa0p = &qa0.x;
    const uint32_t* qa1p = &qa1.x;
    const uint32_t* qa2p = &qa2.x;
    const uint32_t* qa3p = &qa3.x;

    float Oa[16][4];
#pragma unroll
    for (int i = 0; i < 16; ++i)
#pragma unroll
        for (int j = 0; j < 4; ++j) Oa[i][j] = 0.f;
    float lsum0 = 0.f, lsum1 = 0.f;

    for (int ch = 0; ch < 64; ++ch) {
        const int m0 = ch * 64;
        __syncthreads();   // prior chunk's PV reads done before overwrite

        // ---- load K tile [64][32 perm] ----
#pragma unroll
        for (int i = 0; i < 2; ++i) {
            int idx4 = t + i * 256;
            int r = idx4 >> 3, d4 = (idx4 & 7) * 4;
            float4 v = *reinterpret_cast<const float4*>(
                &kbase[(size_t)(m0 + r) * Dd + d4]);
            *reinterpret_cast<float4*>(&smf[KS_W + r * 36 + d4]) = v;
        }
        // ---- load V tile [256][64] (verbatim: perm'd in gmem) ----
#pragma unroll
        for (int i = 0; i < 16; ++i) {
            int idx4 = t + i * 256;
            int c = idx4 >> 4, k4 = (idx4 & 15) * 4;
            float4 v = *reinterpret_cast<const float4*>(
                &vbase[(size_t)c * Nn + m0 + k4]);
            *reinterpret_cast<float4*>(&smf[VS_W + c * 68 + k4]) = v;
        }
        __syncthreads();

        // ---- S = Q K^T : 4 n-tiles x 4 k-steps (LDS.128 B-frags) ----
        float Sa[4][4];
#pragma unroll
        for (int nt = 0; nt < 4; ++nt) {
            Sa[nt][0] = Sa[nt][1] = Sa[nt][2] = Sa[nt][3] = 0.f;
            int nrow = 32 * wc + 8 * nt + g;
            uint4 kb0 = *(const uint4*)&SU[KS_W + nrow * 36 + tg * 8];
            uint4 kb1 = *(const uint4*)&SU[KS_W + nrow * 36 + tg * 8 + 4];
            const uint32_t* kb0p = &kb0.x;
            const uint32_t* kb1p = &kb1.x;
#pragma unroll
            for (int ks = 0; ks < 4; ++ks)
                MMA_TF32(Sa[nt], qa0p[ks], qa1p[ks], qa2p[ks], qa3p[ks],
                         kb0p[ks], kb1p[ks]);
        }

        // ---- exp (no max-sub), tf32-pack into permuted Ps ----
#pragma unroll
        for (int nt = 0; nt < 4; ++nt) {
            int cb  = 32 * wc + 8 * nt + 2 * tg;
            int blk = (cb >> 5) * 32;
            int p0  = blk + perm32(cb & 31);
            int p1  = blk + perm32((cb + 1) & 31);
            float e00 = __expf(Sa[nt][0]);
            float e01 = __expf(Sa[nt][1]);
            float e10 = __expf(Sa[nt][2]);
            float e11 = __expf(Sa[nt][3]);
            lsum0 += e00 + e01;
            lsum1 += e10 + e11;
            SU[PS_W + r0 * 68 + p0] = tf32u(e00);
            SU[PS_W + r0 * 68 + p1] = tf32u(e01);
            SU[PS_W + r1 * 68 + p0] = tf32u(e10);
            SU[PS_W + r1 * 68 + p1] = tf32u(e11);
        }
        __syncthreads();

        // ---- O += P V^T : 16 n-tiles x 8 k-steps (all frags LDS.128) ----
        uint4 pa0 = *(const uint4*)&SU[PS_W + r0 * 68 + tg * 8];
        uint4 pa1 = *(const uint4*)&SU[PS_W + r1 * 68 + tg * 8];
        uint4 pa2 = *(const uint4*)&SU[PS_W + r0 * 68 + tg * 8 + 4];
        uint4 pa3 = *(const uint4*)&SU[PS_W + r1 * 68 + tg * 8 + 4];
        uint4 pb0 = *(const uint4*)&SU[PS_W + r0 * 68 + 32 + tg * 8];
        uint4 pb1 = *(const uint4*)&SU[PS_W + r1 * 68 + 32 + tg * 8];
        uint4 pb2 = *(const uint4*)&SU[PS_W + r0 * 68 + 32 + tg * 8 + 4];
        uint4 pb3 = *(const uint4*)&SU[PS_W + r1 * 68 + 32 + tg * 8 + 4];
        const uint32_t* pa0p = &pa0.x; const uint32_t* pa1p = &pa1.x;
        const uint32_t* pa2p = &pa2.x; const uint32_t* pa3p = &pa3.x;
        const uint32_t* pb0p = &pb0.x; const uint32_t* pb1p = &pb1.x;
        const uint32_t* pb2p = &pb2.x; const uint32_t* pb3p = &pb3.x;
#pragma unroll
        for (int nt = 0; nt < 16; ++nt) {
            int c = 128 * wc + 8 * nt + g;
            uint4 vb0 = *(const uint4*)&SU[VS_W + c * 68 + tg * 8];
            uint4 vb1 = *(const uint4*)&SU[VS_W + c * 68 + tg * 8 + 4];
            uint4 vb2 = *(const uint4*)&SU[VS_W + c * 68 + 32 + tg * 8];
            uint4 vb3 = *(const uint4*)&SU[VS_W + c * 68 + 32 + tg * 8 + 4];
            const uint32_t* vb0p = &vb0.x; const uint32_t* vb1p = &vb1.x;
            const uint32_t* vb2p = &vb2.x; const uint32_t* vb3p = &vb3.x;
#pragma unroll
            for (int ks = 0; ks < 4; ++ks)
                MMA_TF32(Oa[nt], pa0p[ks], pa1p[ks], pa2p[ks], pa3p[ks],
                         vb0p[ks], vb1p[ks]);
#pragma unroll
            for (int ks = 0; ks < 4; ++ks)
                MMA_TF32(Oa[nt], pb0p[ks], pb1p[ks], pb2p[ks], pb3p[ks],
                         vb2p[ks], vb3p[ks]);
        }
    }
    __syncthreads();

    // ---- reduce l: quad shfl, then across the two wc halves via smem ----
    lsum0 += __shfl_xor_sync(0xffffffffu, lsum0, 1);
    lsum0 += __shfl_xor_sync(0xffffffffu, lsum0, 2);
    lsum1 += __shfl_xor_sync(0xffffffffu, lsum1, 1);
    lsum1 += __shfl_xor_sync(0xffffffffu, lsum1, 2);
    if (tg == 0) {
        smf[LR_W + r0 * 2 + wc] = lsum0;
        smf[LR_W + r1 * 2 + wc] = lsum1;
    }
    __syncthreads();
    const float linv0 = 1.0f / (smf[LR_W + r0 * 2] + smf[LR_W + r0 * 2 + 1]);
    const float linv1 = 1.0f / (smf[LR_W + r1 * 2] + smf[LR_W + r1 * 2 + 1]);

    // ---- stage normalized O into [c][r] (stride 68) for coalesced writeback ----
    float* VsO = smf + VS_W;
#pragma unroll
    for (int nt = 0; nt < 16; ++nt) {
        int c0 = 128 * wc + 8 * nt + 2 * tg;
        VsO[c0 * 68 + r0]       = Oa[nt][0] * linv0;
        VsO[(c0 + 1) * 68 + r0] = Oa[nt][1] * linv0;
        VsO[c0 * 68 + r1]       = Oa[nt][2] * linv1;
        VsO[(c0 + 1) * 68 + r1] = Oa[nt][3] * linv1;
    }
    __syncthreads();

    // ---- fused epilogue: out = (gamma*attn + x) * (1 + ga) ----
    const float gm = gammaPtr[0];
#pragma unroll 8
    for (int it = 0; it < 64; ++it) {
        int idx = t + it * 256;
        int c = idx >> 6, r = idx & 63;
        float o  = VsO[c * 68 + r];
        int   bc = b * Cc + c;
        size_t off = (size_t)bc * Nn + n0 + r;
        float res = fmaf(gm, o, x[off]);
        res = fmaf(res, g_ga[bc], res);
        out[off] = res;
    }
}

// =====================================================================
extern "C" void kernel_launch(void* const* d_in, const int* in_sizes, int n_in,
                              void* d_out, int out_size)
{
    const float* x     = (const float*)d_in[0];
    const float* Wq    = (const float*)d_in[1];
    const float* bq    = (const float*)d_in[2];
    const float* Wk    = (const float*)d_in[3];
    const float* bk    = (const float*)d_in[4];
    const float* Wv    = (const float*)d_in[5];
    const float* bv    = (const float*)d_in[6];
    const float* gamma = (const float*)d_in[7];
    const float* Wg1   = (const float*)d_in[8];
    const float* bg1   = (const float*)d_in[9];
    const float* Wg2   = (const float*)d_in[10];
    const float* bg2   = (const float*)d_in[11];
    float* out = (float*)d_out;

    cudaFuncSetAttribute(proj_kernel,      cudaFuncAttributeMaxDynamicSharedMemorySize, PROJ_SMEM);
    cudaFuncSetAttribute(flash_mma_kernel, cudaFuncAttributeMaxDynamicSharedMemorySize, FLASH_SMEM);

    proj_kernel<<<dim3(64, 8), 256, PROJ_SMEM>>>(x, Wq, bq, Wk, bk, Wv, bv);
    gate_kernel<<<8, 256>>>(x, Wg1, bg1, Wg2, bg2);
    flash_mma_kernel<<<dim3(64, 8), 256, FLASH_SMEM>>>(x, gamma, out);
}

// round 14
// speedup vs baseline: 1.0593x; 1.0593x over previous
#include <cuda_runtime.h>
#include <cstdint>

#define Bb 8
#define Cc 256
#define Nn 4096
#define Dd 32

typedef unsigned long long ull;

// ======================= helpers =======================
__device__ __forceinline__ void fma2(ull& d, ull a, ull b) {
    asm("fma.rn.f32x2 %0, %1, %2, %0;" : "+l"(d) : "l"(a), "l"(b));
}
__device__ __forceinline__ ull dup2(float v) {
    ull r; asm("mov.b64 %0, {%1, %1};" : "=l"(r) : "f"(v)); return r;
}
__device__ __forceinline__ float2 unpk2(ull v) {
    float2 r; asm("mov.b64 {%0, %1}, %2;" : "=f"(r.x), "=f"(r.y) : "l"(v)); return r;
}
__device__ __forceinline__ float tf32r(float v) {
    uint32_t u; asm("cvt.rna.tf32.f32 %0, %1;" : "=r"(u) : "f"(v));
    return __uint_as_float(u);
}
__device__ __forceinline__ uint32_t tf32u(float v) {
    uint32_t u; asm("cvt.rna.tf32.f32 %0, %1;" : "=r"(u) : "f"(v));
    return u;
}
// k-fragment permutation within a 32-block: fragment words become contiguous
__device__ __host__ __forceinline__ int perm32(int k) {
    return ((k & 3) << 3) | (k & 4) | (k >> 3);
}

// portable tensor-core mma (sm_80+, assembles at compute_103)
#define MMA_TF32(d, a0, a1, a2, a3, b0, b1) \
    asm volatile("mma.sync.aligned.m16n8k8.row.col.f32.tf32.tf32.f32 " \
        "{%0,%1,%2,%3}, {%4,%5,%6,%7}, {%8,%9}, {%0,%1,%2,%3};" \
        : "+f"((d)[0]), "+f"((d)[1]), "+f"((d)[2]), "+f"((d)[3]) \
        : "r"(a0), "r"(a1), "r"(a2), "r"(a3), "r"(b0), "r"(b1))

// ---- scratch (static device globals) ----
__device__ float g_qT[Bb * Nn * Dd];          // [b][n][d_perm]  tf32
__device__ float g_kT[Bb * Nn * Dd];          // [b][n][d_perm]  tf32
__device__ float g_vC[Bb * Cc * Nn];          // [b][c][n: perm32 in 32-blocks] tf32
__device__ float g_ga[Bb * Cc];               // gate activations

// =====================================================================
// Kernel 1: fused projections q/k/v (f32x2 mainloop). grid (64, 8), 256 thr.
// =====================================================================
#define PROJ_SMEM ((256 * 66 + 64 * 65) * 4)

__global__ __launch_bounds__(256, 2)
void proj_kernel(const float* __restrict__ x,
                 const float* __restrict__ Wq, const float* __restrict__ bq,
                 const float* __restrict__ Wk, const float* __restrict__ bk,
                 const float* __restrict__ Wv, const float* __restrict__ bv)
{
    extern __shared__ float sm[];
    float* xs = sm;              // [256][66]
    float* ws = sm + 256 * 66;   // [64][65]

    const int b  = blockIdx.y;
    const int n0 = blockIdx.x * 64;
    const int t  = threadIdx.x;
    const int tor = t >> 4;
    const int tnc = t & 15;

    const float* xb = x + (size_t)b * Cc * Nn;
#pragma unroll
    for (int i = 0; i < 64; ++i) {
        int idx = t + i * 256;
        int c = idx >> 6, j = idx & 63;
        xs[c * 66 + j] = xb[c * Nn + n0 + j];
    }

    for (int ot = 0; ot < 5; ++ot) {
        ull a2[4][2];
#pragma unroll
        for (int i = 0; i < 4; ++i) { a2[i][0] = 0ULL; a2[i][1] = 0ULL; }

        for (int cc = 0; cc < 4; ++cc) {
            __syncthreads();
#pragma unroll
            for (int i = 0; i < 16; ++i) {
                int idx = t + i * 256;
                int oo = idx >> 6, cj = idx & 63;
                int og = ot * 64 + oo;
                const float* wrow = (og < 32) ? (Wq + og * 256)
                                  : (og < 64) ? (Wk + (og - 32) * 256)
                                              : (Wv + (og - 64) * 256);
                ws[oo * 65 + cj] = wrow[cc * 64 + cj];
            }
            __syncthreads();
#pragma unroll 8
            for (int kk = 0; kk < 64; ++kk) {
                ull xv0 = *reinterpret_cast<const ull*>(&xs[(cc * 64 + kk) * 66 + tnc * 4]);
                ull xv1 = *reinterpret_cast<const ull*>(&xs[(cc * 64 + kk) * 66 + tnc * 4 + 2]);
#pragma unroll
                for (int i = 0; i < 4; ++i) {
                    ull wd = dup2(ws[(tor * 4 + i) * 65 + kk]);
                    fma2(a2[i][0], wd, xv0);
                    fma2(a2[i][1], wd, xv1);
                }
            }
        }
#pragma unroll
        for (int i = 0; i < 4; ++i) {
            int og = ot * 64 + tor * 4 + i;
            float vals[4];
            float2 u0 = unpk2(a2[i][0]), u1 = unpk2(a2[i][1]);
            vals[0] = u0.x; vals[1] = u0.y; vals[2] = u1.x; vals[3] = u1.y;
            if (og < 64) {
                int dp = (og < 32) ? perm32(og) : perm32(og - 32);
#pragma unroll
                for (int j = 0; j < 4; ++j) {
                    int n = n0 + tnc * 4 + j;
                    if (og < 32)
                        g_qT[(b * Nn + n) * Dd + dp] = tf32r(vals[j] + bq[og]);
                    else
                        g_kT[(b * Nn + n) * Dd + dp] = tf32r(vals[j] + bk[og - 32]);
                }
            } else {
                int c = og - 64;
                float bias = bv[c];
#pragma unroll
                for (int j = 0; j < 4; ++j) {
                    int n = n0 + tnc * 4 + j;
                    int np = (n & ~31) | perm32(n & 31);
                    g_vC[((size_t)b * Cc + c) * Nn + np] = tf32r(vals[j] + bias);
                }
            }
        }
    }
}

// =====================================================================
// Kernel 2: gated pooling branch -> g_ga[b][c]
// =====================================================================
__global__ __launch_bounds__(256)
void gate_kernel(const float* __restrict__ x,
                 const float* __restrict__ Wg1, const float* __restrict__ bg1,
                 const float* __restrict__ Wg2, const float* __restrict__ bg2)
{
    __shared__ float gp[256];
    __shared__ float h[32];
    const int b = blockIdx.x;
    const int t = threadIdx.x;
    const int w = t >> 5, lane = t & 31;

    for (int cr = 0; cr < 32; ++cr) {
        int c = w * 32 + cr;
        const float* row = x + ((size_t)b * Cc + c) * Nn;
        float s = 0.f;
        for (int i = lane; i < Nn; i += 32) s += row[i];
#pragma unroll
        for (int o = 16; o; o >>= 1) s += __shfl_down_sync(0xffffffffu, s, o);
        if (lane == 0) gp[c] = s * (1.0f / (float)Nn);
    }
    __syncthreads();
    if (t < 32) {
        float s = bg1[t];
        const float* wr = Wg1 + t * 256;
        for (int c = 0; c < 256; ++c) s = fmaf(wr[c], gp[c], s);
        h[t] = fmaxf(s, 0.f);
    }
    __syncthreads();
    {
        float s = bg2[t];
        const float* wr = Wg2 + t * 32;
#pragma unroll
        for (int o = 0; o < 32; ++o) s = fmaf(wr[o], h[o], s);
        g_ga[b * Cc + t] = 1.0f / (1.0f + __expf(-s));
    }
}

// =====================================================================
// Kernel 3: mma.sync tf32 flash, BM=64, BN=64, LDS.128 permuted fragments,
// register-safe PV scheduling (two k-halves, transient fragments).
// grid (64, 8), 256 threads, 64 chunks.
// smem (words): Qs[64][36] | Ks[64][36] | Vs[256][68] | Ps[64][68] | lred[128]
// =====================================================================
#define QS_W   0
#define KS_W   2304
#define VS_W   4608
#define PS_W   22016
#define LR_W   26368
#define FLASH_SMEM ((26368 + 128) * 4)

__global__ __launch_bounds__(256, 2)
void flash_mma_kernel(const float* __restrict__ x,
                      const float* __restrict__ gammaPtr,
                      float* __restrict__ out)
{
    extern __shared__ float smf[];
    uint32_t* SU = (uint32_t*)smf;

    const int t    = threadIdx.x;
    const int wid  = t >> 5;
    const int lane = t & 31;
    const int g    = lane >> 2;
    const int tg   = lane & 3;
    const int wr   = wid >> 1;      // row band: rows 16*wr .. +15
    const int wc   = wid & 1;       // col half
    const int b    = blockIdx.y;
    const int n0   = blockIdx.x * 64;

    const int r0 = 16 * wr + g;
    const int r1 = r0 + 8;

    const float* vbase = g_vC + (size_t)b * Cc * Nn;
    const float* kbase = g_kT + (size_t)b * Nn * Dd;

    // ---- stage Q (perm'd) -> smem, extract A-fragments (held all kernel) ----
#pragma unroll
    for (int i = 0; i < 2; ++i) {
        int idx4 = t + i * 256;
        int r = idx4 >> 3, d4 = (idx4 & 7) * 4;
        float4 v = *reinterpret_cast<const float4*>(
            &g_qT[((size_t)b * Nn + n0 + r) * Dd + d4]);
        *reinterpret_cast<float4*>(&smf[QS_W + r * 36 + d4]) = v;
    }
    __syncthreads();
    uint4 qa0 = *(const uint4*)&SU[QS_W + r0 * 36 + tg * 8];
    uint4 qa1 = *(const uint4*)&SU[QS_W + r1 * 36 + tg * 8];
    uint4 qa2 = *(const uint4*)&SU[QS_W + r0 * 36 + tg * 8 + 4];
    uint4 qa3 = *(const uint4*)&SU[QS_W + r1 * 36 + tg * 8 + 4];
    const uint32_t* qa0p = &qa0.x;
    const uint32_t* qa1p = &qa1.x;
    const uint32_t* qa2p = &qa2.x;
    const uint32_t* qa3p = &qa3.x;

    float Oa[16][4];
#pragma unroll
    for (int i = 0; i < 16; ++i)
#pragma unroll
        for (int j = 0; j < 4; ++j) Oa[i][j] = 0.f;
    float lsum0 = 0.f, lsum1 = 0.f;

    for (int ch = 0; ch < 64; ++ch) {
        const int m0 = ch * 64;
        __syncthreads();   // prior chunk's PV reads done before overwrite

        // ---- load K tile [64][32 perm] ----
#pragma unroll
        for (int i = 0; i < 2; ++i) {
            int idx4 = t + i * 256;
            int r = idx4 >> 3, d4 = (idx4 & 7) * 4;
            float4 v = *reinterpret_cast<const float4*>(
                &kbase[(size_t)(m0 + r) * Dd + d4]);
            *reinterpret_cast<float4*>(&smf[KS_W + r * 36 + d4]) = v;
        }
        // ---- load V tile [256][64] (verbatim: perm'd in gmem) ----
#pragma unroll
        for (int i = 0; i < 16; ++i) {
            int idx4 = t + i * 256;
            int c = idx4 >> 4, k4 = (idx4 & 15) * 4;
            float4 v = *reinterpret_cast<const float4*>(
                &vbase[(size_t)c * Nn + m0 + k4]);
            *reinterpret_cast<float4*>(&smf[VS_W + c * 68 + k4]) = v;
        }
        __syncthreads();

        // ---- S = Q K^T : 4 n-tiles x 4 k-steps (LDS.128 B-frags) ----
        float Sa[4][4];
#pragma unroll
        for (int nt = 0; nt < 4; ++nt) {
            Sa[nt][0] = Sa[nt][1] = Sa[nt][2] = Sa[nt][3] = 0.f;
            int nrow = 32 * wc + 8 * nt + g;
            uint4 kb0 = *(const uint4*)&SU[KS_W + nrow * 36 + tg * 8];
            uint4 kb1 = *(const uint4*)&SU[KS_W + nrow * 36 + tg * 8 + 4];
            const uint32_t* kb0p = &kb0.x;
            const uint32_t* kb1p = &kb1.x;
#pragma unroll
            for (int ks = 0; ks < 4; ++ks)
                MMA_TF32(Sa[nt], qa0p[ks], qa1p[ks], qa2p[ks], qa3p[ks],
                         kb0p[ks], kb1p[ks]);
        }

        // ---- exp (no max-sub), tf32-pack into permuted Ps ----
#pragma unroll
        for (int nt = 0; nt < 4; ++nt) {
            int cb  = 32 * wc + 8 * nt + 2 * tg;
            int blk = (cb >> 5) * 32;
            int p0  = blk + perm32(cb & 31);
            int p1  = blk + perm32((cb + 1) & 31);
            float e00 = __expf(Sa[nt][0]);
            float e01 = __expf(Sa[nt][1]);
            float e10 = __expf(Sa[nt][2]);
            float e11 = __expf(Sa[nt][3]);
            lsum0 += e00 + e01;
            lsum1 += e10 + e11;
            SU[PS_W + r0 * 68 + p0] = tf32u(e00);
            SU[PS_W + r0 * 68 + p1] = tf32u(e01);
            SU[PS_W + r1 * 68 + p0] = tf32u(e10);
            SU[PS_W + r1 * 68 + p1] = tf32u(e11);
        }
        __syncthreads();

        // ---- O += P V^T : 2 k-halves, transient fragments (no spill) ----
#pragma unroll
        for (int half = 0; half < 2; ++half) {
            const int ho = half * 32;
            uint4 pa0 = *(const uint4*)&SU[PS_W + r0 * 68 + ho + tg * 8];
            uint4 pa1 = *(const uint4*)&SU[PS_W + r1 * 68 + ho + tg * 8];
            uint4 pa2 = *(const uint4*)&SU[PS_W + r0 * 68 + ho + tg * 8 + 4];
            uint4 pa3 = *(const uint4*)&SU[PS_W + r1 * 68 + ho + tg * 8 + 4];
            const uint32_t* pa0p = &pa0.x;
            const uint32_t* pa1p = &pa1.x;
            const uint32_t* pa2p = &pa2.x;
            const uint32_t* pa3p = &pa3.x;
#pragma unroll
            for (int nt = 0; nt < 16; ++nt) {
                int c = 128 * wc + 8 * nt + g;
                uint4 vb0 = *(const uint4*)&SU[VS_W + c * 68 + ho + tg * 8];
                uint4 vb1 = *(const uint4*)&SU[VS_W + c * 68 + ho + tg * 8 + 4];
                const uint32_t* vb0p = &vb0.x;
                const uint32_t* vb1p = &vb1.x;
#pragma unroll
                for (int ks = 0; ks < 4; ++ks)
                    MMA_TF32(Oa[nt], pa0p[ks], pa1p[ks], pa2p[ks], pa3p[ks],
                             vb0p[ks], vb1p[ks]);
            }
        }
    }
    __syncthreads();

    // ---- reduce l: quad shfl, then across the two wc halves via smem ----
    lsum0 += __shfl_xor_sync(0xffffffffu, lsum0, 1);
    lsum0 += __shfl_xor_sync(0xffffffffu, lsum0, 2);
    lsum1 += __shfl_xor_sync(0xffffffffu, lsum1, 1);
    lsum1 += __shfl_xor_sync(0xffffffffu, lsum1, 2);
    if (tg == 0) {
        smf[LR_W + r0 * 2 + wc] = lsum0;
        smf[LR_W + r1 * 2 + wc] = lsum1;
    }
    __syncthreads();
    const float linv0 = 1.0f / (smf[LR_W + r0 * 2] + smf[LR_W + r0 * 2 + 1]);
    const float linv1 = 1.0f / (smf[LR_W + r1 * 2] + smf[LR_W + r1 * 2 + 1]);

    // ---- stage normalized O into [c][r] (stride 68) for coalesced writeback ----
    float* VsO = smf + VS_W;
#pragma unroll
    for (int nt = 0; nt < 16; ++nt) {
        int c0 = 128 * wc + 8 * nt + 2 * tg;
        VsO[c0 * 68 + r0]       = Oa[nt][0] * linv0;
        VsO[(c0 + 1) * 68 + r0] = Oa[nt][1] * linv0;
        VsO[c0 * 68 + r1]       = Oa[nt][2] * linv1;
        VsO[(c0 + 1) * 68 + r1] = Oa[nt][3] * linv1;
    }
    __syncthreads();

    // ---- fused epilogue: out = (gamma*attn + x) * (1 + ga) ----
    const float gm = gammaPtr[0];
#pragma unroll 8
    for (int it = 0; it < 64; ++it) {
        int idx = t + it * 256;
        int c = idx >> 6, r = idx & 63;
        float o  = VsO[c * 68 + r];
        int   bc = b * Cc + c;
        size_t off = (size_t)bc * Nn + n0 + r;
        float res = fmaf(gm, o, x[off]);
        res = fmaf(res, g_ga[bc], res);
        out[off] = res;
    }
}

// =====================================================================
extern "C" void kernel_launch(void* const* d_in, const int* in_sizes, int n_in,
                              void* d_out, int out_size)
{
    const float* x     = (const float*)d_in[0];
    const float* Wq    = (const float*)d_in[1];
    const float* bq    = (const float*)d_in[2];
    const float* Wk    = (const float*)d_in[3];
    const float* bk    = (const float*)d_in[4];
    const float* Wv    = (const float*)d_in[5];
    const float* bv    = (const float*)d_in[6];
    const float* gamma = (const float*)d_in[7];
    const float* Wg1   = (const float*)d_in[8];
    const float* bg1   = (const float*)d_in[9];
    const float* Wg2   = (const float*)d_in[10];
    const float* bg2   = (const float*)d_in[11];
    float* out = (float*)d_out;

    cudaFuncSetAttribute(proj_kernel,      cudaFuncAttributeMaxDynamicSharedMemorySize, PROJ_SMEM);
    cudaFuncSetAttribute(flash_mma_kernel, cudaFuncAttributeMaxDynamicSharedMemorySize, FLASH_SMEM);

    proj_kernel<<<dim3(64, 8), 256, PROJ_SMEM>>>(x, Wq, bq, Wk, bk, Wv, bv);
    gate_kernel<<<8, 256>>>(x, Wg1, bg1, Wg2, bg2);
    flash_mma_kernel<<<dim3(64, 8), 256, FLASH_SMEM>>>(x, gamma, out);
}

// round 15
// speedup vs baseline: 1.3242x; 1.2501x over previous
#include <cuda_runtime.h>
#include <cstdint>

#define Bb 8
#define Cc 256
#define Nn 4096
#define Dd 32

typedef unsigned long long ull;

// ======================= helpers =======================
__device__ __forceinline__ void fma2(ull& d, ull a, ull b) {
    asm("fma.rn.f32x2 %0, %1, %2, %0;" : "+l"(d) : "l"(a), "l"(b));
}
__device__ __forceinline__ ull dup2(float v) {
    ull r; asm("mov.b64 %0, {%1, %1};" : "=l"(r) : "f"(v)); return r;
}
__device__ __forceinline__ float2 unpk2(ull v) {
    float2 r; asm("mov.b64 {%0, %1}, %2;" : "=f"(r.x), "=f"(r.y) : "l"(v)); return r;
}
__device__ __forceinline__ float tf32r(float v) {
    uint32_t u; asm("cvt.rna.tf32.f32 %0, %1;" : "=r"(u) : "f"(v));
    return __uint_as_float(u);
}
__device__ __forceinline__ uint32_t tf32u(float v) {
    uint32_t u; asm("cvt.rna.tf32.f32 %0, %1;" : "=r"(u) : "f"(v));
    return u;
}

// portable tensor-core mma (sm_80+, assembles at compute_103)
#define MMA_TF32(d, a0, a1, a2, a3, b0, b1) \
    asm volatile("mma.sync.aligned.m16n8k8.row.col.f32.tf32.tf32.f32 " \
        "{%0,%1,%2,%3}, {%4,%5,%6,%7}, {%8,%9}, {%0,%1,%2,%3};" \
        : "+f"((d)[0]), "+f"((d)[1]), "+f"((d)[2]), "+f"((d)[3]) \
        : "r"(a0), "r"(a1), "r"(a2), "r"(a3), "r"(b0), "r"(b1))

// ---- scratch (static device globals) ----
__device__ float g_qT[Bb * Nn * Dd];          // [b][n][d]  tf32
__device__ float g_kT[Bb * Nn * Dd];          // [b][n][d]  tf32
__device__ float g_vC[Bb * Cc * Nn];          // [b][c][n]  tf32
__device__ float g_ga[Bb * Cc];               // gate activations

// =====================================================================
// Kernel 1: fused projections q/k/v (f32x2 mainloop). grid (64, 8), 256 thr.
// (R11 version: plain layouts)
// =====================================================================
#define PROJ_SMEM ((256 * 66 + 64 * 65) * 4)

__global__ __launch_bounds__(256, 2)
void proj_kernel(const float* __restrict__ x,
                 const float* __restrict__ Wq, const float* __restrict__ bq,
                 const float* __restrict__ Wk, const float* __restrict__ bk,
                 const float* __restrict__ Wv, const float* __restrict__ bv)
{
    extern __shared__ float sm[];
    float* xs = sm;              // [256][66]
    float* ws = sm + 256 * 66;   // [64][65]

    const int b  = blockIdx.y;
    const int n0 = blockIdx.x * 64;
    const int t  = threadIdx.x;
    const int tor = t >> 4;
    const int tnc = t & 15;

    const float* xb = x + (size_t)b * Cc * Nn;
#pragma unroll
    for (int i = 0; i < 64; ++i) {
        int idx = t + i * 256;
        int c = idx >> 6, j = idx & 63;
        xs[c * 66 + j] = xb[c * Nn + n0 + j];
    }

    for (int ot = 0; ot < 5; ++ot) {
        ull a2[4][2];
#pragma unroll
        for (int i = 0; i < 4; ++i) { a2[i][0] = 0ULL; a2[i][1] = 0ULL; }

        for (int cc = 0; cc < 4; ++cc) {
            __syncthreads();
#pragma unroll
            for (int i = 0; i < 16; ++i) {
                int idx = t + i * 256;
                int oo = idx >> 6, cj = idx & 63;
                int og = ot * 64 + oo;
                const float* wrow = (og < 32) ? (Wq + og * 256)
                                  : (og < 64) ? (Wk + (og - 32) * 256)
                                              : (Wv + (og - 64) * 256);
                ws[oo * 65 + cj] = wrow[cc * 64 + cj];
            }
            __syncthreads();
#pragma unroll 8
            for (int kk = 0; kk < 64; ++kk) {
                ull xv0 = *reinterpret_cast<const ull*>(&xs[(cc * 64 + kk) * 66 + tnc * 4]);
                ull xv1 = *reinterpret_cast<const ull*>(&xs[(cc * 64 + kk) * 66 + tnc * 4 + 2]);
#pragma unroll
                for (int i = 0; i < 4; ++i) {
                    ull wd = dup2(ws[(tor * 4 + i) * 65 + kk]);
                    fma2(a2[i][0], wd, xv0);
                    fma2(a2[i][1], wd, xv1);
                }
            }
        }
#pragma unroll
        for (int i = 0; i < 4; ++i) {
            int og = ot * 64 + tor * 4 + i;
            float vals[4];
            float2 u0 = unpk2(a2[i][0]), u1 = unpk2(a2[i][1]);
            vals[0] = u0.x; vals[1] = u0.y; vals[2] = u1.x; vals[3] = u1.y;
            if (og < 64) {
#pragma unroll
                for (int j = 0; j < 4; ++j) {
                    int n = n0 + tnc * 4 + j;
                    if (og < 32)
                        g_qT[(b * Nn + n) * Dd + og] = tf32r(vals[j] + bq[og]);
                    else
                        g_kT[(b * Nn + n) * Dd + (og - 32)] = tf32r(vals[j] + bk[og - 32]);
                }
            } else {
                int c = og - 64;
                float bias = bv[c];
                float4 w;
                w.x = tf32r(vals[0] + bias); w.y = tf32r(vals[1] + bias);
                w.z = tf32r(vals[2] + bias); w.w = tf32r(vals[3] + bias);
                *reinterpret_cast<float4*>(
                    &g_vC[((size_t)b * Cc + c) * Nn + n0 + tnc * 4]) = w;
            }
        }
    }
}

// =====================================================================
// Kernel 2: gated pooling branch -> g_ga[b][c]
// =====================================================================
__global__ __launch_bounds__(256)
void gate_kernel(const float* __restrict__ x,
                 const float* __restrict__ Wg1, const float* __restrict__ bg1,
                 const float* __restrict__ Wg2, const float* __restrict__ bg2)
{
    __shared__ float gp[256];
    __shared__ float h[32];
    const int b = blockIdx.x;
    const int t = threadIdx.x;
    const int w = t >> 5, lane = t & 31;

    for (int cr = 0; cr < 32; ++cr) {
        int c = w * 32 + cr;
        const float* row = x + ((size_t)b * Cc + c) * Nn;
        float s = 0.f;
        for (int i = lane; i < Nn; i += 32) s += row[i];
#pragma unroll
        for (int o = 16; o; o >>= 1) s += __shfl_down_sync(0xffffffffu, s, o);
        if (lane == 0) gp[c] = s * (1.0f / (float)Nn);
    }
    __syncthreads();
    if (t < 32) {
        float s = bg1[t];
        const float* wr = Wg1 + t * 256;
        for (int c = 0; c < 256; ++c) s = fmaf(wr[c], gp[c], s);
        h[t] = fmaxf(s, 0.f);
    }
    __syncthreads();
    {
        float s = bg2[t];
        const float* wr = Wg2 + t * 32;
#pragma unroll
        for (int o = 0; o < 32; ++o) s = fmaf(wr[o], h[o], s);
        g_ga[b * Cc + t] = 1.0f / (1.0f + __expf(-s));
    }
}

// =====================================================================
// Kernel 3: mma.sync tf32 flash, BM=128 q rows, c-split (2 halves).
// grid (32, 2, 8), 256 threads, 64 kv-chunks of 64.
// Warp grid: 4 m-groups (32 rows each = 2x m16) x 2 groups (S-col / O-col).
// Every K/V B-fragment feeds 2 MMAs -> half the smem B-frag bytes of R11.
// smem (words): Qs[128][36] | Ks[64][36] | Vs[128][68] | Ps[128][68] | LR[256]
// =====================================================================
#define QS_W   0
#define KS_W   4608
#define VS_W   6912
#define PS_W   15616
#define LR_W   24320
#define FLASH_SMEM (24576 * 4)

__global__ __launch_bounds__(256, 2)
void flash_mma_kernel(const float* __restrict__ x,
                      const float* __restrict__ gammaPtr,
                      float* __restrict__ out)
{
    extern __shared__ float smf[];
    uint32_t* SU = (uint32_t*)smf;

    const int t    = threadIdx.x;
    const int wid  = t >> 5;
    const int lane = t & 31;
    const int g    = lane >> 2;
    const int tg   = lane & 3;
    const int mg   = wid >> 1;      // m-group: rows 32*mg .. +31
    const int cg   = wid & 1;       // column group (S: kv-cols, PV: c-cols)
    const int b    = blockIdx.z;
    const int by   = blockIdx.y;    // c-half: channels 128*by .. +127
    const int n0   = blockIdx.x * 128;

    const float* vbase = g_vC + ((size_t)b * Cc + 128 * by) * Nn;
    const float* kbase = g_kT + (size_t)b * Nn * Dd;

    // ---- stage Q tile [128 rows][32 d] ----
#pragma unroll
    for (int i = 0; i < 4; ++i) {
        int idx4 = t + i * 256;
        int r = idx4 >> 3, d4 = (idx4 & 7) * 4;
        float4 v = *reinterpret_cast<const float4*>(
            &g_qT[((size_t)b * Nn + n0 + r) * Dd + d4]);
        *reinterpret_cast<float4*>(&smf[QS_W + r * 36 + d4]) = v;
    }

    float Oa[2][8][4];
#pragma unroll
    for (int mt = 0; mt < 2; ++mt)
#pragma unroll
        for (int nt = 0; nt < 8; ++nt)
#pragma unroll
            for (int j = 0; j < 4; ++j) Oa[mt][nt][j] = 0.f;
    float ls[2][2] = {{0.f, 0.f}, {0.f, 0.f}};

    for (int ch = 0; ch < 64; ++ch) {
        const int m0 = ch * 64;
        __syncthreads();   // prior chunk's PV reads done before overwrite

        // ---- load K tile [64][32] ----
#pragma unroll
        for (int i = 0; i < 2; ++i) {
            int idx4 = t + i * 256;
            int r = idx4 >> 3, d4 = (idx4 & 7) * 4;
            float4 v = *reinterpret_cast<const float4*>(
                &kbase[(size_t)(m0 + r) * Dd + d4]);
            *reinterpret_cast<float4*>(&smf[KS_W + r * 36 + d4]) = v;
        }
        // ---- load V half-tile [128 c][64 k] ----
#pragma unroll
        for (int i = 0; i < 8; ++i) {
            int idx4 = t + i * 256;
            int c = idx4 >> 4, k4 = (idx4 & 15) * 4;
            float4 v = *reinterpret_cast<const float4*>(
                &vbase[(size_t)c * Nn + m0 + k4]);
            *reinterpret_cast<float4*>(&smf[VS_W + c * 68 + k4]) = v;
        }
        __syncthreads();

        // ---- S = Q K^T : 2 m-tiles x 4 n-tiles, B-frag shared across m ----
        float Sa[2][4][4];
#pragma unroll
        for (int mt = 0; mt < 2; ++mt)
#pragma unroll
            for (int nt = 0; nt < 4; ++nt)
#pragma unroll
                for (int j = 0; j < 4; ++j) Sa[mt][nt][j] = 0.f;
#pragma unroll
        for (int ks = 0; ks < 4; ++ks) {
            uint32_t qa[2][4];
#pragma unroll
            for (int mt = 0; mt < 2; ++mt) {
                int qb = QS_W + (32 * mg + 16 * mt + g) * 36 + 8 * ks + tg;
                qa[mt][0] = SU[qb];
                qa[mt][1] = SU[qb + 8 * 36];
                qa[mt][2] = SU[qb + 4];
                qa[mt][3] = SU[qb + 8 * 36 + 4];
            }
#pragma unroll
            for (int nt = 0; nt < 4; ++nt) {
                int nb = KS_W + (32 * cg + 8 * nt + g) * 36 + 8 * ks + tg;
                uint32_t b0 = SU[nb];
                uint32_t b1 = SU[nb + 4];
                MMA_TF32(Sa[0][nt], qa[0][0], qa[0][1], qa[0][2], qa[0][3], b0, b1);
                MMA_TF32(Sa[1][nt], qa[1][0], qa[1][1], qa[1][2], qa[1][3], b0, b1);
            }
        }

        // ---- exp (no max-sub), tf32-pack into Ps, accumulate l ----
#pragma unroll
        for (int mt = 0; mt < 2; ++mt) {
#pragma unroll
            for (int nt = 0; nt < 4; ++nt) {
                int row0 = 32 * mg + 16 * mt + g;
                int row1 = row0 + 8;
                int col  = 32 * cg + 8 * nt + 2 * tg;
                float e00 = __expf(Sa[mt][nt][0]);
                float e01 = __expf(Sa[mt][nt][1]);
                float e10 = __expf(Sa[mt][nt][2]);
                float e11 = __expf(Sa[mt][nt][3]);
                ls[mt][0] += e00 + e01;
                ls[mt][1] += e10 + e11;
                SU[PS_W + row0 * 68 + col]     = tf32u(e00);
                SU[PS_W + row0 * 68 + col + 1] = tf32u(e01);
                SU[PS_W + row1 * 68 + col]     = tf32u(e10);
                SU[PS_W + row1 * 68 + col + 1] = tf32u(e11);
            }
        }
        __syncthreads();

        // ---- O += P V^T : 2 m-tiles x 8 n-tiles, B-frag shared across m ----
#pragma unroll
        for (int ks = 0; ks < 8; ++ks) {
            uint32_t pa[2][4];
#pragma unroll
            for (int mt = 0; mt < 2; ++mt) {
                int pb = PS_W + (32 * mg + 16 * mt + g) * 68 + 8 * ks + tg;
                pa[mt][0] = SU[pb];
                pa[mt][1] = SU[pb + 8 * 68];
                pa[mt][2] = SU[pb + 4];
                pa[mt][3] = SU[pb + 8 * 68 + 4];
            }
#pragma unroll
            for (int nt = 0; nt < 8; ++nt) {
                int vb = VS_W + (64 * cg + 8 * nt + g) * 68 + 8 * ks + tg;
                uint32_t b0 = SU[vb];
                uint32_t b1 = SU[vb + 4];
                MMA_TF32(Oa[0][nt], pa[0][0], pa[0][1], pa[0][2], pa[0][3], b0, b1);
                MMA_TF32(Oa[1][nt], pa[1][0], pa[1][1], pa[1][2], pa[1][3], b0, b1);
            }
        }
    }
    __syncthreads();

    // ---- reduce l: quad shfl over tg, then across the two cg halves ----
#pragma unroll
    for (int mt = 0; mt < 2; ++mt)
#pragma unroll
        for (int h = 0; h < 2; ++h) {
            float v = ls[mt][h];
            v += __shfl_xor_sync(0xffffffffu, v, 1);
            v += __shfl_xor_sync(0xffffffffu, v, 2);
            ls[mt][h] = v;
        }
    if (tg == 0) {
#pragma unroll
        for (int mt = 0; mt < 2; ++mt)
#pragma unroll
            for (int h = 0; h < 2; ++h) {
                int row = 32 * mg + 16 * mt + 8 * h + g;
                smf[LR_W + row * 2 + cg] = ls[mt][h];
            }
    }
    __syncthreads();
    float linv[2][2];
#pragma unroll
    for (int mt = 0; mt < 2; ++mt)
#pragma unroll
        for (int h = 0; h < 2; ++h) {
            int row = 32 * mg + 16 * mt + 8 * h + g;
            linv[mt][h] = 1.0f / (smf[LR_W + row * 2] + smf[LR_W + row * 2 + 1]);
        }

    // ---- stage normalized O into [c_local][row] (stride 132) ----
    float* VsO = smf + VS_W;
#pragma unroll
    for (int mt = 0; mt < 2; ++mt) {
#pragma unroll
        for (int nt = 0; nt < 8; ++nt) {
            int c0   = 64 * cg + 8 * nt + 2 * tg;
            int row0 = 32 * mg + 16 * mt + g;
            int row1 = row0 + 8;
            VsO[c0 * 132 + row0]       = Oa[mt][nt][0] * linv[mt][0];
            VsO[(c0 + 1) * 132 + row0] = Oa[mt][nt][1] * linv[mt][0];
            VsO[c0 * 132 + row1]       = Oa[mt][nt][2] * linv[mt][1];
            VsO[(c0 + 1) * 132 + row1] = Oa[mt][nt][3] * linv[mt][1];
        }
    }
    __syncthreads();

    // ---- fused epilogue: out = (gamma*attn + x) * (1 + ga) ----
    const float gm = gammaPtr[0];
#pragma unroll 8
    for (int it = 0; it < 64; ++it) {
        int idx = t + it * 256;
        int c = idx >> 7, r = idx & 127;
        float o  = VsO[c * 132 + r];
        int   bc = b * Cc + 128 * by + c;
        size_t off = (size_t)bc * Nn + n0 + r;
        float res = fmaf(gm, o, x[off]);
        res = fmaf(res, g_ga[bc], res);
        out[off] = res;
    }
}

// =====================================================================
extern "C" void kernel_launch(void* const* d_in, const int* in_sizes, int n_in,
                              void* d_out, int out_size)
{
    const float* x     = (const float*)d_in[0];
    const float* Wq    = (const float*)d_in[1];
    const float* bq    = (const float*)d_in[2];
    const float* Wk    = (const float*)d_in[3];
    const float* bk    = (const float*)d_in[4];
    const float* Wv    = (const float*)d_in[5];
    const float* bv    = (const float*)d_in[6];
    const float* gamma = (const float*)d_in[7];
    const float* Wg1   = (const float*)d_in[8];
    const float* bg1   = (const float*)d_in[9];
    const float* Wg2   = (const float*)d_in[10];
    const float* bg2   = (const float*)d_in[11];
    float* out = (float*)d_out;

    cudaFuncSetAttribute(proj_kernel,      cudaFuncAttributeMaxDynamicSharedMemorySize, PROJ_SMEM);
    cudaFuncSetAttribute(flash_mma_kernel, cudaFuncAttributeMaxDynamicSharedMemorySize, FLASH_SMEM);

    proj_kernel<<<dim3(64, 8), 256, PROJ_SMEM>>>(x, Wq, bq, Wk, bk, Wv, bv);
    gate_kernel<<<8, 256>>>(x, Wg1, bg1, Wg2, bg2);
    flash_mma_kernel<<<dim3(32, 2, 8), 256, FLASH_SMEM>>>(x, gamma, out);
}

// round 16
// speedup vs baseline: 1.5468x; 1.1681x over previous
#include <cuda_runtime.h>
#include <cstdint>

#define Bb 8
#define Cc 256
#define Nn 4096
#define Dd 32

typedef unsigned long long ull;

// ======================= helpers =======================
__device__ __forceinline__ float tf32r(float v) {
    uint32_t u; asm("cvt.rna.tf32.f32 %0, %1;" : "=r"(u) : "f"(v));
    return __uint_as_float(u);
}
__device__ __forceinline__ uint32_t tf32u(float v) {
    uint32_t u; asm("cvt.rna.tf32.f32 %0, %1;" : "=r"(u) : "f"(v));
    return u;
}

// portable tensor-core mma (sm_80+, assembles at compute_103)
#define MMA_TF32(d, a0, a1, a2, a3, b0, b1) \
    asm volatile("mma.sync.aligned.m16n8k8.row.col.f32.tf32.tf32.f32 " \
        "{%0,%1,%2,%3}, {%4,%5,%6,%7}, {%8,%9}, {%0,%1,%2,%3};" \
        : "+f"((d)[0]), "+f"((d)[1]), "+f"((d)[2]), "+f"((d)[3]) \
        : "r"(a0), "r"(a1), "r"(a2), "r"(a3), "r"(b0), "r"(b1))

// ---- scratch (static device globals) ----
__device__ float g_qT[Bb * Nn * Dd];          // [b][n][d]  tf32
__device__ float g_kT[Bb * Nn * Dd];          // [b][n][d]  tf32
__device__ float g_vC[Bb * Cc * Nn];          // [b][c][n]  tf32
__device__ float g_ga[Bb * Cc];               // gate activations

// =====================================================================
// Kernel 1: tensor-core projections. grid (32, 8), 256 threads, 1 CTA/SM.
// O[320 x 128n] = [Wq;Wk;Wv] @ x_tile, 5 passes of 64 rows, k=256 in 8 chunks.
// smem: xs[128n][260] (x^T, tf32, XOR-swizzled c)  |  ws[64o][260] (W pass tile)
// =====================================================================
#define PXS_W 0
#define PWS_W (128 * 260)
#define PROJ_SMEM ((128 * 260 + 64 * 260) * 4)

__global__ __launch_bounds__(256, 1)
void proj_mma_kernel(const float* __restrict__ x,
                     const float* __restrict__ Wq, const float* __restrict__ bq,
                     const float* __restrict__ Wk, const float* __restrict__ bk,
                     const float* __restrict__ Wv, const float* __restrict__ bv)
{
    extern __shared__ float smf[];
    uint32_t* SU = (uint32_t*)smf;

    const int t    = threadIdx.x;
    const int wid  = t >> 5;
    const int lane = t & 31;
    const int g    = lane >> 2;
    const int tg   = lane & 3;
    const int wm   = wid >> 2;      // 0..1  m-half (rows 32*wm..+31 of pass)
    const int wc   = wid & 3;       // 0..3  n-quarter (cols 32*wc..+31)
    const int b    = blockIdx.y;
    const int n0   = blockIdx.x * 128;

    // ---- load x tile [256c][128n], store transposed+swizzled xs[n][c'] ----
    const float* xb = x + (size_t)b * Cc * Nn + n0;
    for (int i = 0; i < 128; ++i) {
        int idx = t + i * 256;
        int c = idx >> 7, n = idx & 127;
        float v = xb[(size_t)c * Nn + n];
        smf[PXS_W + n * 260 + (c ^ (8 * ((n >> 3) & 3)))] = tf32r(v);
    }

    for (int pass = 0; pass < 5; ++pass) {
        __syncthreads();   // prior pass done with ws / os region
        // ---- load W pass tile [64o][256c] -> ws (tf32) ----
        for (int i = 0; i < 16; ++i) {
            int idx = t + i * 256;
            int o = idx >> 6, c4 = (idx & 63) * 4;
            int og = pass * 64 + o;
            const float* wrow = (og < 32) ? (Wq + og * 256)
                              : (og < 64) ? (Wk + (og - 32) * 256)
                                          : (Wv + (og - 64) * 256);
            float4 w = *reinterpret_cast<const float4*>(wrow + c4);
            float* d = &smf[PWS_W + o * 260 + c4];
            d[0] = tf32r(w.x); d[1] = tf32r(w.y);
            d[2] = tf32r(w.z); d[3] = tf32r(w.w);
        }
        __syncthreads();

        float acc[2][4][4];
#pragma unroll
        for (int mt = 0; mt < 2; ++mt)
#pragma unroll
            for (int nt = 0; nt < 4; ++nt)
#pragma unroll
                for (int j = 0; j < 4; ++j) acc[mt][nt][j] = 0.f;

        // ---- mainloop: 8 k-chunks x 4 k-steps ----
        for (int kc = 0; kc < 8; ++kc) {
            const int kb = kc * 32;
#pragma unroll
            for (int ks = 0; ks < 4; ++ks) {
                uint32_t a[2][4];
#pragma unroll
                for (int mt = 0; mt < 2; ++mt) {
                    int ab = PWS_W + (32 * wm + 16 * mt + g) * 260 + kb + 8 * ks + tg;
                    a[mt][0] = SU[ab];
                    a[mt][1] = SU[ab + 8 * 260];
                    a[mt][2] = SU[ab + 4];
                    a[mt][3] = SU[ab + 8 * 260 + 4];
                }
#pragma unroll
                for (int nt = 0; nt < 4; ++nt) {
                    int swk = ks ^ (nt & 3);
                    int nb = PXS_W + (32 * wc + 8 * nt + g) * 260 + kb + 8 * swk + tg;
                    uint32_t b0 = SU[nb], b1 = SU[nb + 4];
                    MMA_TF32(acc[0][nt], a[0][0], a[0][1], a[0][2], a[0][3], b0, b1);
                    MMA_TF32(acc[1][nt], a[1][0], a[1][1], a[1][2], a[1][3], b0, b1);
                }
            }
        }

        // ---- epilogue ----
        if (pass == 0) {
            // q/k: stage [n][og] in ws region, then coalesced writeback
            __syncthreads();   // all warps done reading ws
            float* os = smf + PWS_W;   // [128n][68]
            float bias[2][2];
#pragma unroll
            for (int mt = 0; mt < 2; ++mt)
#pragma unroll
                for (int h = 0; h < 2; ++h) {
                    int row = 32 * wm + 16 * mt + 8 * h + g;
                    bias[mt][h] = (row < 32) ? bq[row] : bk[row - 32];
                }
#pragma unroll
            for (int mt = 0; mt < 2; ++mt)
#pragma unroll
                for (int nt = 0; nt < 4; ++nt) {
                    int col  = 32 * wc + 8 * nt + 2 * tg;
                    int row0 = 32 * wm + 16 * mt + g;
                    int row1 = row0 + 8;
                    os[col * 68 + row0]       = tf32r(acc[mt][nt][0] + bias[mt][0]);
                    os[(col + 1) * 68 + row0] = tf32r(acc[mt][nt][1] + bias[mt][0]);
                    os[col * 68 + row1]       = tf32r(acc[mt][nt][2] + bias[mt][1]);
                    os[(col + 1) * 68 + row1] = tf32r(acc[mt][nt][3] + bias[mt][1]);
                }
            __syncthreads();
#pragma unroll
            for (int i = 0; i < 8; ++i) {
                int idx = t + i * 256;
                int n = idx >> 4, d4 = (idx & 15) * 4;
                float4 v = *reinterpret_cast<const float4*>(&os[n * 68 + d4]);
                if (d4 < 32)
                    *reinterpret_cast<float4*>(
                        &g_qT[((size_t)b * Nn + n0 + n) * Dd + d4]) = v;
                else
                    *reinterpret_cast<float4*>(
                        &g_kT[((size_t)b * Nn + n0 + n) * Dd + (d4 - 32)]) = v;
            }
        } else {
            // v: direct writes, [c][n] layout, float2 along n
            const int cb = (pass - 1) * 64;
#pragma unroll
            for (int mt = 0; mt < 2; ++mt) {
                int c0 = cb + 32 * wm + 16 * mt + g;
                int c1 = c0 + 8;
                float b0v = bv[c0], b1v = bv[c1];
#pragma unroll
                for (int nt = 0; nt < 4; ++nt) {
                    int n = n0 + 32 * wc + 8 * nt + 2 * tg;
                    float2 v0, v1;
                    v0.x = tf32r(acc[mt][nt][0] + b0v);
                    v0.y = tf32r(acc[mt][nt][1] + b0v);
                    v1.x = tf32r(acc[mt][nt][2] + b1v);
                    v1.y = tf32r(acc[mt][nt][3] + b1v);
                    *reinterpret_cast<float2*>(
                        &g_vC[((size_t)b * Cc + c0) * Nn + n]) = v0;
                    *reinterpret_cast<float2*>(
                        &g_vC[((size_t)b * Cc + c1) * Nn + n]) = v1;
                }
            }
        }
    }
}

// =====================================================================
// Kernel 2: gated pooling branch -> g_ga[b][c]
// =====================================================================
__global__ __launch_bounds__(256)
void gate_kernel(const float* __restrict__ x,
                 const float* __restrict__ Wg1, const float* __restrict__ bg1,
                 const float* __restrict__ Wg2, const float* __restrict__ bg2)
{
    __shared__ float gp[256];
    __shared__ float h[32];
    const int b = blockIdx.x;
    const int t = threadIdx.x;
    const int w = t >> 5, lane = t & 31;

    for (int cr = 0; cr < 32; ++cr) {
        int c = w * 32 + cr;
        const float* row = x + ((size_t)b * Cc + c) * Nn;
        float s = 0.f;
        for (int i = lane; i < Nn; i += 32) s += row[i];
#pragma unroll
        for (int o = 16; o; o >>= 1) s += __shfl_down_sync(0xffffffffu, s, o);
        if (lane == 0) gp[c] = s * (1.0f / (float)Nn);
    }
    __syncthreads();
    if (t < 32) {
        float s = bg1[t];
        const float* wr = Wg1 + t * 256;
        for (int c = 0; c < 256; ++c) s = fmaf(wr[c], gp[c], s);
        h[t] = fmaxf(s, 0.f);
    }
    __syncthreads();
    {
        float s = bg2[t];
        const float* wr = Wg2 + t * 32;
#pragma unroll
        for (int o = 0; o < 32; ++o) s = fmaf(wr[o], h[o], s);
        g_ga[b * Cc + t] = 1.0f / (1.0f + __expf(-s));
    }
}

// =====================================================================
// Kernel 3: mma.sync tf32 flash, BM=128 q rows, c-split (2 halves).
// (unchanged from R15 — proven 931 us config)
// =====================================================================
#define QS_W   0
#define KS_W   4608
#define VS_W   6912
#define PS_W   15616
#define LR_W   24320
#define FLASH_SMEM (24576 * 4)

__global__ __launch_bounds__(256, 2)
void flash_mma_kernel(const float* __restrict__ x,
                      const float* __restrict__ gammaPtr,
                      float* __restrict__ out)
{
    extern __shared__ float smf[];
    uint32_t* SU = (uint32_t*)smf;

    const int t    = threadIdx.x;
    const int wid  = t >> 5;
    const int lane = t & 31;
    const int g    = lane >> 2;
    const int tg   = lane & 3;
    const int mg   = wid >> 1;      // m-group: rows 32*mg .. +31
    const int cg   = wid & 1;       // column group (S: kv-cols, PV: c-cols)
    const int b    = blockIdx.z;
    const int by   = blockIdx.y;    // c-half: channels 128*by .. +127
    const int n0   = blockIdx.x * 128;

    const float* vbase = g_vC + ((size_t)b * Cc + 128 * by) * Nn;
    const float* kbase = g_kT + (size_t)b * Nn * Dd;

    // ---- stage Q tile [128 rows][32 d] ----
#pragma unroll
    for (int i = 0; i < 4; ++i) {
        int idx4 = t + i * 256;
        int r = idx4 >> 3, d4 = (idx4 & 7) * 4;
        float4 v = *reinterpret_cast<const float4*>(
            &g_qT[((size_t)b * Nn + n0 + r) * Dd + d4]);
        *reinterpret_cast<float4*>(&smf[QS_W + r * 36 + d4]) = v;
    }

    float Oa[2][8][4];
#pragma unroll
    for (int mt = 0; mt < 2; ++mt)
#pragma unroll
        for (int nt = 0; nt < 8; ++nt)
#pragma unroll
            for (int j = 0; j < 4; ++j) Oa[mt][nt][j] = 0.f;
    float ls[2][2] = {{0.f, 0.f}, {0.f, 0.f}};

    for (int ch = 0; ch < 64; ++ch) {
        const int m0 = ch * 64;
        __syncthreads();   // prior chunk's PV reads done before overwrite

        // ---- load K tile [64][32] ----
#pragma unroll
        for (int i = 0; i < 2; ++i) {
            int idx4 = t + i * 256;
            int r = idx4 >> 3, d4 = (idx4 & 7) * 4;
            float4 v = *reinterpret_cast<const float4*>(
                &kbase[(size_t)(m0 + r) * Dd + d4]);
            *reinterpret_cast<float4*>(&smf[KS_W + r * 36 + d4]) = v;
        }
        // ---- load V half-tile [128 c][64 k] ----
#pragma unroll
        for (int i = 0; i < 8; ++i) {
            int idx4 = t + i * 256;
            int c = idx4 >> 4, k4 = (idx4 & 15) * 4;
            float4 v = *reinterpret_cast<const float4*>(
                &vbase[(size_t)c * Nn + m0 + k4]);
            *reinterpret_cast<float4*>(&smf[VS_W + c * 68 + k4]) = v;
        }
        __syncthreads();

        // ---- S = Q K^T : 2 m-tiles x 4 n-tiles, B-frag shared across m ----
        float Sa[2][4][4];
#pragma unroll
        for (int mt = 0; mt < 2; ++mt)
#pragma unroll
            for (int nt = 0; nt < 4; ++nt)
#pragma unroll
                for (int j = 0; j < 4; ++j) Sa[mt][nt][j] = 0.f;
#pragma unroll
        for (int ks = 0; ks < 4; ++ks) {
            uint32_t qa[2][4];
#pragma unroll
            for (int mt = 0; mt < 2; ++mt) {
                int qb = QS_W + (32 * mg + 16 * mt + g) * 36 + 8 * ks + tg;
                qa[mt][0] = SU[qb];
                qa[mt][1] = SU[qb + 8 * 36];
                qa[mt][2] = SU[qb + 4];
                qa[mt][3] = SU[qb + 8 * 36 + 4];
            }
#pragma unroll
            for (int nt = 0; nt < 4; ++nt) {
                int nb = KS_W + (32 * cg + 8 * nt + g) * 36 + 8 * ks + tg;
                uint32_t b0 = SU[nb];
                uint32_t b1 = SU[nb + 4];
                MMA_TF32(Sa[0][nt], qa[0][0], qa[0][1], qa[0][2], qa[0][3], b0, b1);
                MMA_TF32(Sa[1][nt], qa[1][0], qa[1][1], qa[1][2], qa[1][3], b0, b1);
            }
        }

        // ---- exp (no max-sub), tf32-pack into Ps, accumulate l ----
#pragma unroll
        for (int mt = 0; mt < 2; ++mt) {
#pragma unroll
            for (int nt = 0; nt < 4; ++nt) {
                int row0 = 32 * mg + 16 * mt + g;
                int row1 = row0 + 8;
                int col  = 32 * cg + 8 * nt + 2 * tg;
                float e00 = __expf(Sa[mt][nt][0]);
                float e01 = __expf(Sa[mt][nt][1]);
                float e10 = __expf(Sa[mt][nt][2]);
                float e11 = __expf(Sa[mt][nt][3]);
                ls[mt][0] += e00 + e01;
                ls[mt][1] += e10 + e11;
                SU[PS_W + row0 * 68 + col]     = tf32u(e00);
                SU[PS_W + row0 * 68 + col + 1] = tf32u(e01);
                SU[PS_W + row1 * 68 + col]     = tf32u(e10);
                SU[PS_W + row1 * 68 + col + 1] = tf32u(e11);
            }
        }
        __syncthreads();

        // ---- O += P V^T : 2 m-tiles x 8 n-tiles, B-frag shared across m ----
#pragma unroll
        for (int ks = 0; ks < 8; ++ks) {
            uint32_t pa[2][4];
#pragma unroll
            for (int mt = 0; mt < 2; ++mt) {
                int pb = PS_W + (32 * mg + 16 * mt + g) * 68 + 8 * ks + tg;
                pa[mt][0] = SU[pb];
                pa[mt][1] = SU[pb + 8 * 68];
                pa[mt][2] = SU[pb + 4];
                pa[mt][3] = SU[pb + 8 * 68 + 4];
            }
#pragma unroll
            for (int nt = 0; nt < 8; ++nt) {
                int vb = VS_W + (64 * cg + 8 * nt + g) * 68 + 8 * ks + tg;
                uint32_t b0 = SU[vb];
                uint32_t b1 = SU[vb + 4];
                MMA_TF32(Oa[0][nt], pa[0][0], pa[0][1], pa[0][2], pa[0][3], b0, b1);
                MMA_TF32(Oa[1][nt], pa[1][0], pa[1][1], pa[1][2], pa[1][3], b0, b1);
            }
        }
    }
    __syncthreads();

    // ---- reduce l: quad shfl over tg, then across the two cg halves ----
#pragma unroll
    for (int mt = 0; mt < 2; ++mt)
#pragma unroll
        for (int h = 0; h < 2; ++h) {
            float v = ls[mt][h];
            v += __shfl_xor_sync(0xffffffffu, v, 1);
            v += __shfl_xor_sync(0xffffffffu, v, 2);
            ls[mt][h] = v;
        }
    if (tg == 0) {
#pragma unroll
        for (int mt = 0; mt < 2; ++mt)
#pragma unroll
            for (int h = 0; h < 2; ++h) {
                int row = 32 * mg + 16 * mt + 8 * h + g;
                smf[LR_W + row * 2 + cg] = ls[mt][h];
            }
    }
    __syncthreads();
    float linv[2][2];
#pragma unroll
    for (int mt = 0; mt < 2; ++mt)
#pragma unroll
        for (int h = 0; h < 2; ++h) {
            int row = 32 * mg + 16 * mt + 8 * h + g;
            linv[mt][h] = 1.0f / (smf[LR_W + row * 2] + smf[LR_W + row * 2 + 1]);
        }

    // ---- stage normalized O into [c_local][row] (stride 132) ----
    float* VsO = smf + VS_W;
#pragma unroll
    for (int mt = 0; mt < 2; ++mt) {
#pragma unroll
        for (int nt = 0; nt < 8; ++nt) {
            int c0   = 64 * cg + 8 * nt + 2 * tg;
            int row0 = 32 * mg + 16 * mt + g;
            int row1 = row0 + 8;
            VsO[c0 * 132 + row0]       = Oa[mt][nt][0] * linv[mt][0];
            VsO[(c0 + 1) * 132 + row0] = Oa[mt][nt][1] * linv[mt][0];
            VsO[c0 * 132 + row1]       = Oa[mt][nt][2] * linv[mt][1];
            VsO[(c0 + 1) * 132 + row1] = Oa[mt][nt][3] * linv[mt][1];
        }
    }
    __syncthreads();

    // ---- fused epilogue: out = (gamma*attn + x) * (1 + ga) ----
    const float gm = gammaPtr[0];
#pragma unroll 8
    for (int it = 0; it < 64; ++it) {
        int idx = t + it * 256;
        int c = idx >> 7, r = idx & 127;
        float o  = VsO[c * 132 + r];
        int   bc = b * Cc + 128 * by + c;
        size_t off = (size_t)bc * Nn + n0 + r;
        float res = fmaf(gm, o, x[off]);
        res = fmaf(res, g_ga[bc], res);
        out[off] = res;
    }
}

// =====================================================================
extern "C" void kernel_launch(void* const* d_in, const int* in_sizes, int n_in,
                              void* d_out, int out_size)
{
    const float* x     = (const float*)d_in[0];
    const float* Wq    = (const float*)d_in[1];
    const float* bq    = (const float*)d_in[2];
    const float* Wk    = (const float*)d_in[3];
    const float* bk    = (const float*)d_in[4];
    const float* Wv    = (const float*)d_in[5];
    const float* bv    = (const float*)d_in[6];
    const float* gamma = (const float*)d_in[7];
    const float* Wg1   = (const float*)d_in[8];
    const float* bg1   = (const float*)d_in[9];
    const float* Wg2   = (const float*)d_in[10];
    const float* bg2   = (const float*)d_in[11];
    float* out = (float*)d_out;

    cudaFuncSetAttribute(proj_mma_kernel,  cudaFuncAttributeMaxDynamicSharedMemorySize, PROJ_SMEM);
    cudaFuncSetAttribute(flash_mma_kernel, cudaFuncAttributeMaxDynamicSharedMemorySize, FLASH_SMEM);

    proj_mma_kernel<<<dim3(32, 8), 256, PROJ_SMEM>>>(x, Wq, bq, Wk, bk, Wv, bv);
    gate_kernel<<<8, 256>>>(x, Wg1, bg1, Wg2, bg2);
    flash_mma_kernel<<<dim3(32, 2, 8), 256, FLASH_SMEM>>>(x, gamma, out);
}

// round 17
// speedup vs baseline: 2.0398x; 1.3188x over previous
#include <cuda_runtime.h>
#include <cstdint>

#define Bb 8
#define Cc 256
#define Nn 4096
#define Dd 32

typedef unsigned long long ull;

// ======================= helpers =======================
__device__ __forceinline__ float tf32r(float v) {
    uint32_t u; asm("cvt.rna.tf32.f32 %0, %1;" : "=r"(u) : "f"(v));
    return __uint_as_float(u);
}
__device__ __forceinline__ uint32_t tf32u(float v) {
    uint32_t u; asm("cvt.rna.tf32.f32 %0, %1;" : "=r"(u) : "f"(v));
    return u;
}
// pack two f32 -> bf16x2 word {lo, hi}
__device__ __forceinline__ uint32_t bf16pk(float lo, float hi) {
    uint32_t r; asm("cvt.rn.bf16x2.f32 %0, %1, %2;" : "=r"(r) : "f"(hi), "f"(lo));
    return r;
}

// portable tensor-core mmas (sm_80+, assemble at compute_103)
#define MMA_TF32(d, a0, a1, a2, a3, b0, b1) \
    asm volatile("mma.sync.aligned.m16n8k8.row.col.f32.tf32.tf32.f32 " \
        "{%0,%1,%2,%3}, {%4,%5,%6,%7}, {%8,%9}, {%0,%1,%2,%3};" \
        : "+f"((d)[0]), "+f"((d)[1]), "+f"((d)[2]), "+f"((d)[3]) \
        : "r"(a0), "r"(a1), "r"(a2), "r"(a3), "r"(b0), "r"(b1))

#define MMA_BF16(d, a0, a1, a2, a3, b0, b1) \
    asm volatile("mma.sync.aligned.m16n8k16.row.col.f32.bf16.bf16.f32 " \
        "{%0,%1,%2,%3}, {%4,%5,%6,%7}, {%8,%9}, {%0,%1,%2,%3};" \
        : "+f"((d)[0]), "+f"((d)[1]), "+f"((d)[2]), "+f"((d)[3]) \
        : "r"(a0), "r"(a1), "r"(a2), "r"(a3), "r"(b0), "r"(b1))

// ---- scratch (static device globals) ----
__device__ float    g_qT[Bb * Nn * Dd];          // [b][n][d]  tf32
__device__ float    g_kT[Bb * Nn * Dd];          // [b][n][d]  tf32
__device__ uint32_t g_vC2[Bb * Cc * (Nn / 2)];   // [b][c][n/2] bf16x2 pairs
__device__ float    g_ga[Bb * Cc];               // gate activations

// =====================================================================
// Kernel 1: tensor-core projections. grid (32, 8), 256 threads, 1 CTA/SM.
// O[320 x 128n] = [Wq;Wk;Wv] @ x_tile, 5 passes of 64 rows, k=256 in 8 chunks.
// smem: xs[128n][260] (x^T, tf32, XOR-swizzled c)  |  ws[64o][260]
// =====================================================================
#define PXS_W 0
#define PWS_W (128 * 260)
#define PROJ_SMEM ((128 * 260 + 64 * 260) * 4)

__global__ __launch_bounds__(256, 1)
void proj_mma_kernel(const float* __restrict__ x,
                     const float* __restrict__ Wq, const float* __restrict__ bq,
                     const float* __restrict__ Wk, const float* __restrict__ bk,
                     const float* __restrict__ Wv, const float* __restrict__ bv)
{
    extern __shared__ float smf[];
    uint32_t* SU = (uint32_t*)smf;

    const int t    = threadIdx.x;
    const int wid  = t >> 5;
    const int lane = t & 31;
    const int g    = lane >> 2;
    const int tg   = lane & 3;
    const int wm   = wid >> 2;      // 0..1  m-half (rows 32*wm..+31 of pass)
    const int wc   = wid & 3;       // 0..3  n-quarter (cols 32*wc..+31)
    const int b    = blockIdx.y;
    const int n0   = blockIdx.x * 128;

    // ---- load x tile [256c][128n], store transposed+swizzled xs[n][c'] ----
    const float* xb = x + (size_t)b * Cc * Nn + n0;
    for (int i = 0; i < 128; ++i) {
        int idx = t + i * 256;
        int c = idx >> 7, n = idx & 127;
        float v = xb[(size_t)c * Nn + n];
        smf[PXS_W + n * 260 + (c ^ (8 * ((n >> 3) & 3)))] = tf32r(v);
    }

    for (int pass = 0; pass < 5; ++pass) {
        __syncthreads();   // prior pass done with ws / os region
        // ---- load W pass tile [64o][256c] -> ws (tf32) ----
        for (int i = 0; i < 16; ++i) {
            int idx = t + i * 256;
            int o = idx >> 6, c4 = (idx & 63) * 4;
            int og = pass * 64 + o;
            const float* wrow = (og < 32) ? (Wq + og * 256)
                              : (og < 64) ? (Wk + (og - 32) * 256)
                                          : (Wv + (og - 64) * 256);
            float4 w = *reinterpret_cast<const float4*>(wrow + c4);
            float* d = &smf[PWS_W + o * 260 + c4];
            d[0] = tf32r(w.x); d[1] = tf32r(w.y);
            d[2] = tf32r(w.z); d[3] = tf32r(w.w);
        }
        __syncthreads();

        float acc[2][4][4];
#pragma unroll
        for (int mt = 0; mt < 2; ++mt)
#pragma unroll
            for (int nt = 0; nt < 4; ++nt)
#pragma unroll
                for (int j = 0; j < 4; ++j) acc[mt][nt][j] = 0.f;

        // ---- mainloop: 8 k-chunks x 4 k-steps ----
        for (int kc = 0; kc < 8; ++kc) {
            const int kb = kc * 32;
#pragma unroll
            for (int ks = 0; ks < 4; ++ks) {
                uint32_t a[2][4];
#pragma unroll
                for (int mt = 0; mt < 2; ++mt) {
                    int ab = PWS_W + (32 * wm + 16 * mt + g) * 260 + kb + 8 * ks + tg;
                    a[mt][0] = SU[ab];
                    a[mt][1] = SU[ab + 8 * 260];
                    a[mt][2] = SU[ab + 4];
                    a[mt][3] = SU[ab + 8 * 260 + 4];
                }
#pragma unroll
                for (int nt = 0; nt < 4; ++nt) {
                    int swk = ks ^ (nt & 3);
                    int nb = PXS_W + (32 * wc + 8 * nt + g) * 260 + kb + 8 * swk + tg;
                    uint32_t b0 = SU[nb], b1 = SU[nb + 4];
                    MMA_TF32(acc[0][nt], a[0][0], a[0][1], a[0][2], a[0][3], b0, b1);
                    MMA_TF32(acc[1][nt], a[1][0], a[1][1], a[1][2], a[1][3], b0, b1);
                }
            }
        }

        // ---- epilogue ----
        if (pass == 0) {
            // q/k: stage [n][og] in ws region, then coalesced writeback
            __syncthreads();   // all warps done reading ws
            float* os = smf + PWS_W;   // [128n][68]
            float bias[2][2];
#pragma unroll
            for (int mt = 0; mt < 2; ++mt)
#pragma unroll
                for (int h = 0; h < 2; ++h) {
                    int row = 32 * wm + 16 * mt + 8 * h + g;
                    bias[mt][h] = (row < 32) ? bq[row] : bk[row - 32];
                }
#pragma unroll
            for (int mt = 0; mt < 2; ++mt)
#pragma unroll
                for (int nt = 0; nt < 4; ++nt) {
                    int col  = 32 * wc + 8 * nt + 2 * tg;
                    int row0 = 32 * wm + 16 * mt + g;
                    int row1 = row0 + 8;
                    os[col * 68 + row0]       = tf32r(acc[mt][nt][0] + bias[mt][0]);
                    os[(col + 1) * 68 + row0] = tf32r(acc[mt][nt][1] + bias[mt][0]);
                    os[col * 68 + row1]       = tf32r(acc[mt][nt][2] + bias[mt][1]);
                    os[(col + 1) * 68 + row1] = tf32r(acc[mt][nt][3] + bias[mt][1]);
                }
            __syncthreads();
#pragma unroll
            for (int i = 0; i < 8; ++i) {
                int idx = t + i * 256;
                int n = idx >> 4, d4 = (idx & 15) * 4;
                float4 v = *reinterpret_cast<const float4*>(&os[n * 68 + d4]);
                if (d4 < 32)
                    *reinterpret_cast<float4*>(
                        &g_qT[((size_t)b * Nn + n0 + n) * Dd + d4]) = v;
                else
                    *reinterpret_cast<float4*>(
                        &g_kT[((size_t)b * Nn + n0 + n) * Dd + (d4 - 32)]) = v;
            }
        } else {
            // v: direct bf16x2 writes, [c][n/2] layout
            const int cb = (pass - 1) * 64;
#pragma unroll
            for (int mt = 0; mt < 2; ++mt) {
                int c0 = cb + 32 * wm + 16 * mt + g;
                int c1 = c0 + 8;
                float b0v = bv[c0], b1v = bv[c1];
#pragma unroll
                for (int nt = 0; nt < 4; ++nt) {
                    int nw = n0 / 2 + 16 * wc + 4 * nt + tg;
                    g_vC2[((size_t)b * Cc + c0) * (Nn / 2) + nw] =
                        bf16pk(acc[mt][nt][0] + b0v, acc[mt][nt][1] + b0v);
                    g_vC2[((size_t)b * Cc + c1) * (Nn / 2) + nw] =
                        bf16pk(acc[mt][nt][2] + b1v, acc[mt][nt][3] + b1v);
                }
            }
        }
    }
}

// =====================================================================
// Kernel 2: gated pooling branch -> g_ga[b][c]
// =====================================================================
__global__ __launch_bounds__(256)
void gate_kernel(const float* __restrict__ x,
                 const float* __restrict__ Wg1, const float* __restrict__ bg1,
                 const float* __restrict__ Wg2, const float* __restrict__ bg2)
{
    __shared__ float gp[256];
    __shared__ float h[32];
    const int b = blockIdx.x;
    const int t = threadIdx.x;
    const int w = t >> 5, lane = t & 31;

    for (int cr = 0; cr < 32; ++cr) {
        int c = w * 32 + cr;
        const float* row = x + ((size_t)b * Cc + c) * Nn;
        float s = 0.f;
        for (int i = lane; i < Nn; i += 32) s += row[i];
#pragma unroll
        for (int o = 16; o; o >>= 1) s += __shfl_down_sync(0xffffffffu, s, o);
        if (lane == 0) gp[c] = s * (1.0f / (float)Nn);
    }
    __syncthreads();
    if (t < 32) {
        float s = bg1[t];
        const float* wr = Wg1 + t * 256;
        for (int c = 0; c < 256; ++c) s = fmaf(wr[c], gp[c], s);
        h[t] = fmaxf(s, 0.f);
    }
    __syncthreads();
    {
        float s = bg2[t];
        const float* wr = Wg2 + t * 32;
#pragma unroll
        for (int o = 0; o < 32; ++o) s = fmaf(wr[o], h[o], s);
        g_ga[b * Cc + t] = 1.0f / (1.0f + __expf(-s));
    }
}

// =====================================================================
// Kernel 3: flash attention. S-phase tf32 (unchanged), PV-phase bf16.
// grid (32, 2, 8), 256 threads, 64 kv-chunks of 64.
// smem (words): Qs[128][36] f32 | Ks[64][36] f32 | Vs[128][36] bf16x2
//               Ps[128][36] bf16x2 | OS overlays [0,16896) | LR @16896
// =====================================================================
#define QS_W   0
#define KS_W   4608
#define VS_W   6912
#define PS_W   11520
#define OS_W   0
#define LR_W   16896
#define FLASH_SMEM ((16896 + 256) * 4)

__global__ __launch_bounds__(256, 2)
void flash_mma_kernel(const float* __restrict__ x,
                      const float* __restrict__ gammaPtr,
                      float* __restrict__ out)
{
    extern __shared__ float smf[];
    uint32_t* SU = (uint32_t*)smf;

    const int t    = threadIdx.x;
    const int wid  = t >> 5;
    const int lane = t & 31;
    const int g    = lane >> 2;
    const int tg   = lane & 3;
    const int mg   = wid >> 1;      // m-group: rows 32*mg .. +31
    const int cg   = wid & 1;       // column group (S: kv-cols, PV: c-cols)
    const int b    = blockIdx.z;
    const int by   = blockIdx.y;    // c-half: channels 128*by .. +127
    const int n0   = blockIdx.x * 128;

    const uint32_t* vbase = g_vC2 + ((size_t)b * Cc + 128 * by) * (Nn / 2);
    const float*    kbase = g_kT + (size_t)b * Nn * Dd;

    // ---- stage Q tile [128 rows][32 d] ----
#pragma unroll
    for (int i = 0; i < 4; ++i) {
        int idx4 = t + i * 256;
        int r = idx4 >> 3, d4 = (idx4 & 7) * 4;
        float4 v = *reinterpret_cast<const float4*>(
            &g_qT[((size_t)b * Nn + n0 + r) * Dd + d4]);
        *reinterpret_cast<float4*>(&smf[QS_W + r * 36 + d4]) = v;
    }

    float Oa[2][8][4];
#pragma unroll
    for (int mt = 0; mt < 2; ++mt)
#pragma unroll
        for (int nt = 0; nt < 8; ++nt)
#pragma unroll
            for (int j = 0; j < 4; ++j) Oa[mt][nt][j] = 0.f;
    float ls[2][2] = {{0.f, 0.f}, {0.f, 0.f}};

    for (int ch = 0; ch < 64; ++ch) {
        const int m0 = ch * 64;
        __syncthreads();   // prior chunk's PV reads done before overwrite

        // ---- load K tile [64][32] f32 ----
#pragma unroll
        for (int i = 0; i < 2; ++i) {
            int idx4 = t + i * 256;
            int r = idx4 >> 3, d4 = (idx4 & 7) * 4;
            float4 v = *reinterpret_cast<const float4*>(
                &kbase[(size_t)(m0 + r) * Dd + d4]);
            *reinterpret_cast<float4*>(&smf[KS_W + r * 36 + d4]) = v;
        }
        // ---- load V half-tile [128 c][64 k] bf16 (32 words/row) ----
#pragma unroll
        for (int i = 0; i < 4; ++i) {
            int idx4 = t + i * 256;
            int c = idx4 >> 3, w4 = (idx4 & 7) * 4;
            uint4 v = *reinterpret_cast<const uint4*>(
                &vbase[(size_t)c * (Nn / 2) + m0 / 2 + w4]);
            *reinterpret_cast<uint4*>(&SU[VS_W + c * 36 + w4]) = v;
        }
        __syncthreads();

        // ---- S = Q K^T : tf32, 2 m-tiles x 4 n-tiles (unchanged) ----
        float Sa[2][4][4];
#pragma unroll
        for (int mt = 0; mt < 2; ++mt)
#pragma unroll
            for (int nt = 0; nt < 4; ++nt)
#pragma unroll
                for (int j = 0; j < 4; ++j) Sa[mt][nt][j] = 0.f;
#pragma unroll
        for (int ks = 0; ks < 4; ++ks) {
            uint32_t qa[2][4];
#pragma unroll
            for (int mt = 0; mt < 2; ++mt) {
                int qb = QS_W + (32 * mg + 16 * mt + g) * 36 + 8 * ks + tg;
                qa[mt][0] = SU[qb];
                qa[mt][1] = SU[qb + 8 * 36];
                qa[mt][2] = SU[qb + 4];
                qa[mt][3] = SU[qb + 8 * 36 + 4];
            }
#pragma unroll
            for (int nt = 0; nt < 4; ++nt) {
                int nb = KS_W + (32 * cg + 8 * nt + g) * 36 + 8 * ks + tg;
                uint32_t b0 = SU[nb];
                uint32_t b1 = SU[nb + 4];
                MMA_TF32(Sa[0][nt], qa[0][0], qa[0][1], qa[0][2], qa[0][3], b0, b1);
                MMA_TF32(Sa[1][nt], qa[1][0], qa[1][1], qa[1][2], qa[1][3], b0, b1);
            }
        }

        // ---- exp (no max-sub), pack bf16x2 into Ps, accumulate l ----
#pragma unroll
        for (int mt = 0; mt < 2; ++mt) {
#pragma unroll
            for (int nt = 0; nt < 4; ++nt) {
                int row0 = 32 * mg + 16 * mt + g;
                int row1 = row0 + 8;
                int colw = 16 * cg + 4 * nt + tg;
                float e00 = __expf(Sa[mt][nt][0]);
                float e01 = __expf(Sa[mt][nt][1]);
                float e10 = __expf(Sa[mt][nt][2]);
                float e11 = __expf(Sa[mt][nt][3]);
                ls[mt][0] += e00 + e01;
                ls[mt][1] += e10 + e11;
                SU[PS_W + row0 * 36 + colw] = bf16pk(e00, e01);
                SU[PS_W + row1 * 36 + colw] = bf16pk(e10, e11);
            }
        }
        __syncthreads();

        // ---- O += P V^T : bf16 k16, 4 k-steps, B-frag shared across m ----
#pragma unroll
        for (int ks = 0; ks < 4; ++ks) {
            uint32_t pa[2][4];
#pragma unroll
            for (int mt = 0; mt < 2; ++mt) {
                int pb = PS_W + (32 * mg + 16 * mt + g) * 36 + 8 * ks + tg;
                pa[mt][0] = SU[pb];
                pa[mt][1] = SU[pb + 8 * 36];
                pa[mt][2] = SU[pb + 4];
                pa[mt][3] = SU[pb + 8 * 36 + 4];
            }
#pragma unroll
            for (int nt = 0; nt < 8; ++nt) {
                int vb = VS_W + (64 * cg + 8 * nt + g) * 36 + 8 * ks + tg;
                uint32_t b0 = SU[vb];
                uint32_t b1 = SU[vb + 4];
                MMA_BF16(Oa[0][nt], pa[0][0], pa[0][1], pa[0][2], pa[0][3], b0, b1);
                MMA_BF16(Oa[1][nt], pa[1][0], pa[1][1], pa[1][2], pa[1][3], b0, b1);
            }
        }
    }
    __syncthreads();

    // ---- reduce l: quad shfl over tg, then across the two cg halves ----
#pragma unroll
    for (int mt = 0; mt < 2; ++mt)
#pragma unroll
        for (int h = 0; h < 2; ++h) {
            float v = ls[mt][h];
            v += __shfl_xor_sync(0xffffffffu, v, 1);
            v += __shfl_xor_sync(0xffffffffu, v, 2);
            ls[mt][h] = v;
        }
    if (tg == 0) {
#pragma unroll
        for (int mt = 0; mt < 2; ++mt)
#pragma unroll
            for (int h = 0; h < 2; ++h) {
                int row = 32 * mg + 16 * mt + 8 * h + g;
                smf[LR_W + row * 2 + cg] = ls[mt][h];
            }
    }
    __syncthreads();
    float linv[2][2];
#pragma unroll
    for (int mt = 0; mt < 2; ++mt)
#pragma unroll
        for (int h = 0; h < 2; ++h) {
            int row = 32 * mg + 16 * mt + 8 * h + g;
            linv[mt][h] = 1.0f / (smf[LR_W + row * 2] + smf[LR_W + row * 2 + 1]);
        }

    // ---- stage normalized O into [c_local][row] (stride 132, overlays) ----
    float* VsO = smf + OS_W;
#pragma unroll
    for (int mt = 0; mt < 2; ++mt) {
#pragma unroll
        for (int nt = 0; nt < 8; ++nt) {
            int c0   = 64 * cg + 8 * nt + 2 * tg;
            int row0 = 32 * mg + 16 * mt + g;
            int row1 = row0 + 8;
            VsO[c0 * 132 + row0]       = Oa[mt][nt][0] * linv[mt][0];
            VsO[(c0 + 1) * 132 + row0] = Oa[mt][nt][1] * linv[mt][0];
            VsO[c0 * 132 + row1]       = Oa[mt][nt][2] * linv[mt][1];
            VsO[(c0 + 1) * 132 + row1] = Oa[mt][nt][3] * linv[mt][1];
        }
    }
    __syncthreads();

    // ---- fused epilogue: out = (gamma*attn + x) * (1 + ga) ----
    const float gm = gammaPtr[0];
#pragma unroll 8
    for (int it = 0; it < 64; ++it) {
        int idx = t + it * 256;
        int c = idx >> 7, r = idx & 127;
        float o  = VsO[c * 132 + r];
        int   bc = b * Cc + 128 * by + c;
        size_t off = (size_t)bc * Nn + n0 + r;
        float res = fmaf(gm, o, x[off]);
        res = fmaf(res, g_ga[bc], res);
        out[off] = res;
    }
}

// =====================================================================
extern "C" void kernel_launch(void* const* d_in, const int* in_sizes, int n_in,
                              void* d_out, int out_size)
{
    const float* x     = (const float*)d_in[0];
    const float* Wq    = (const float*)d_in[1];
    const float* bq    = (const float*)d_in[2];
    const float* Wk    = (const float*)d_in[3];
    const float* bk    = (const float*)d_in[4];
    const float* Wv    = (const float*)d_in[5];
    const float* bv    = (const float*)d_in[6];
    const float* gamma = (const float*)d_in[7];
    const float* Wg1   = (const float*)d_in[8];
    const float* bg1   = (const float*)d_in[9];
    const float* Wg2   = (const float*)d_in[10];
    const float* bg2   = (const float*)d_in[11];
    float* out = (float*)d_out;

    cudaFuncSetAttribute(proj_mma_kernel,  cudaFuncAttributeMaxDynamicSharedMemorySize, PROJ_SMEM);
    cudaFuncSetAttribute(flash_mma_kernel, cudaFuncAttributeMaxDynamicSharedMemorySize, FLASH_SMEM);

    proj_mma_kernel<<<dim3(32, 8), 256, PROJ_SMEM>>>(x, Wq, bq, Wk, bk, Wv, bv);
    gate_kernel<<<8, 256>>>(x, Wg1, bg1, Wg2, bg2);
    flash_mma_kernel<<<dim3(32, 2, 8), 256, FLASH_SMEM>>>(x, gamma, out);
}